// round 1
// baseline (speedup 1.0000x reference)
#include <cuda_runtime.h>
#include <math.h>

#define NN   8192
#define DIN  256
#define DOUT 128

// Scratch (no allocations allowed)
__device__ float g_h[NN * DOUT];          // 4 MB, fp32 h
__device__ float g_a1[NN], g_a2[NN];
__device__ float g_e1p[NN], g_e1n[NN];    // exp(a1), exp(0.01*a1)
__device__ float g_e2p[NN], g_e2n[NN];    // exp(a2), exp(0.01*a2)

// ---- packed f32x2 helpers (Blackwell FFMA2) ----
__device__ __forceinline__ unsigned long long fma2(unsigned long long a,
                                                   unsigned long long b,
                                                   unsigned long long c) {
    unsigned long long d;
    asm("fma.rn.f32x2 %0, %1, %2, %3;" : "=l"(d) : "l"(a), "l"(b), "l"(c));
    return d;
}
__device__ __forceinline__ unsigned long long pack2(float x, float y) {
    unsigned long long d;
    asm("mov.b64 %0, {%1, %2};" : "=l"(d) : "f"(x), "f"(y));
    return d;
}
__device__ __forceinline__ void unpack2(unsigned long long v, float& x, float& y) {
    asm("mov.b64 {%0, %1}, %2;" : "=f"(x), "=f"(y) : "l"(v));
}

// ============================================================
// Kernel 1: h = feat @ W^T + b   (8192x256 @ 256x128)
// 128 blocks x 256 threads; BM=64, BN=128(all), BK=32
// ============================================================
__global__ __launch_bounds__(256) void gemm_h_kernel(
    const float* __restrict__ feat,
    const float* __restrict__ W,
    const float* __restrict__ bias)
{
    __shared__ float fs[64][32];     // feat tile
    __shared__ float ws[32][132];    // W^T tile, padded (132*4=528B rows, 16B-aligned)

    const int t  = threadIdx.x;
    const int i0 = blockIdx.x * 64;
    const int ty = t >> 4, tx = t & 15;   // rows ty*4..+3, cols tx*8..+7

    float acc[4][8];
#pragma unroll
    for (int r = 0; r < 4; r++)
#pragma unroll
        for (int c = 0; c < 8; c++) acc[r][c] = 0.f;

    for (int k0 = 0; k0 < DIN; k0 += 32) {
        // load feat tile: 512 float4
#pragma unroll
        for (int v = 0; v < 2; v++) {
            int f   = v * 256 + t;
            int row = f >> 3;
            int off = (f & 7) * 4;
            *(float4*)&fs[row][off] =
                *(const float4*)&feat[(size_t)(i0 + row) * DIN + k0 + off];
        }
        // load W tile transposed: ws[kk][c] = W[c][k0+kk]
        {
            int c    = t >> 1;
            int half = (t & 1) * 16;
#pragma unroll
            for (int q = 0; q < 4; q++) {
                float4 wv = *(const float4*)&W[(size_t)c * DIN + k0 + half + q * 4];
                ws[half + q * 4 + 0][c] = wv.x;
                ws[half + q * 4 + 1][c] = wv.y;
                ws[half + q * 4 + 2][c] = wv.z;
                ws[half + q * 4 + 3][c] = wv.w;
            }
        }
        __syncthreads();

#pragma unroll
        for (int kk = 0; kk < 32; kk++) {
            float a[4];
#pragma unroll
            for (int r = 0; r < 4; r++) a[r] = fs[ty * 4 + r][kk];
            float4 b0 = *(const float4*)&ws[kk][tx * 8];
            float4 b1 = *(const float4*)&ws[kk][tx * 8 + 4];
            float bb[8] = {b0.x, b0.y, b0.z, b0.w, b1.x, b1.y, b1.z, b1.w};
#pragma unroll
            for (int r = 0; r < 4; r++)
#pragma unroll
                for (int c = 0; c < 8; c++) acc[r][c] += a[r] * bb[c];
        }
        __syncthreads();
    }

#pragma unroll
    for (int r = 0; r < 4; r++) {
        int gi = i0 + ty * 4 + r;
#pragma unroll
        for (int c = 0; c < 8; c++)
            g_h[(size_t)gi * DOUT + tx * 8 + c] = acc[r][c] + bias[tx * 8 + c];
    }
}

// ============================================================
// Kernel 2: a1,a2 + exp tables.  1024 blocks x 256 (8 rows/block, 1 warp/row)
// ============================================================
__global__ __launch_bounds__(256) void prep_kernel(
    const float* __restrict__ w1, const float* __restrict__ b1,
    const float* __restrict__ w2, const float* __restrict__ b2)
{
    const int warp = threadIdx.x >> 5;
    const int lane = threadIdx.x & 31;
    const int i    = blockIdx.x * 8 + warp;

    float s1 = 0.f, s2 = 0.f;
#pragma unroll
    for (int d = lane; d < DOUT; d += 32) {
        float hv = g_h[(size_t)i * DOUT + d];
        s1 += hv * w1[d];
        s2 += hv * w2[d];
    }
#pragma unroll
    for (int o = 16; o > 0; o >>= 1) {
        s1 += __shfl_xor_sync(0xffffffffu, s1, o);
        s2 += __shfl_xor_sync(0xffffffffu, s2, o);
    }
    if (lane == 0) {
        float a1 = s1 + b1[0];
        float a2 = s2 + b2[0];
        g_a1[i]  = a1;
        g_a2[i]  = a2;
        g_e1p[i] = expf(a1);
        g_e1n[i] = expf(0.01f * a1);
        g_e2p[i] = expf(a2);
        g_e2n[i] = expf(0.01f * a2);
    }
}

// ============================================================
// Kernel 3: fused masked-softmax attention aggregate.
// out[i,:] = (sum_j w_ij h[j,:]) / (sum_j w_ij)
// w_ij = adj_ij * ( (a1_i+a2_j>=0) ? e1p_i*e2p_j : e1n_i*e2n_j )
// 128 blocks x 256 threads; BM=64 rows, BJ=32 per iter, full 128 cols.
// ============================================================
__global__ __launch_bounds__(256) void attn_kernel(
    const int* __restrict__ adj, float* __restrict__ out)
{
    __shared__ float hs[32][128];    // 16 KB
    __shared__ float w_s[64][33];    // padded: conflict-free writes
    __shared__ float den_s[64];

    const int t  = threadIdx.x;
    const int i0 = blockIdx.x * 64;

    // weight-gen mapping: one row per thread-quad
    const int wrow = t >> 2;
    const int wj   = (t & 3) * 8;
    const int gi   = i0 + wrow;
    const float a1r  = g_a1[gi];
    const float e1pr = g_e1p[gi];
    const float e1nr = g_e1n[gi];
    const int* adjrow = adj + (size_t)gi * NN + wj;
    float den = 0.f;

    // FMA mapping: 4 rows x 8 cols per thread
    const int ty = t >> 4, tx = t & 15;
    unsigned long long acc[4][4];
#pragma unroll
    for (int r = 0; r < 4; r++)
#pragma unroll
        for (int c = 0; c < 4; c++) acc[r][c] = pack2(0.f, 0.f);

    for (int j0 = 0; j0 < NN; j0 += 32) {
        // ---- stage: load h tile + compute weight tile ----
        // (sync at top protects previous iteration's reads)
        __syncthreads();
#pragma unroll
        for (int v = 0; v < 4; v++) {
            int f   = v * 256 + t;
            int row = f >> 5;
            int off = (f & 31) * 4;
            *(float4*)&hs[row][off] =
                *(const float4*)&g_h[(size_t)(j0 + row) * DOUT + off];
        }
        // per-thread: 8 weights for (row wrow, j0+wj .. +7)
        {
            int4 A0 = *(const int4*)(adjrow + j0);
            int4 A1 = *(const int4*)(adjrow + j0 + 4);
            int av[8] = {A0.x, A0.y, A0.z, A0.w, A1.x, A1.y, A1.z, A1.w};
            float4 a2v0  = *(const float4*)&g_a2[j0 + wj];
            float4 a2v1  = *(const float4*)&g_a2[j0 + wj + 4];
            float4 e2pv0 = *(const float4*)&g_e2p[j0 + wj];
            float4 e2pv1 = *(const float4*)&g_e2p[j0 + wj + 4];
            float4 e2nv0 = *(const float4*)&g_e2n[j0 + wj];
            float4 e2nv1 = *(const float4*)&g_e2n[j0 + wj + 4];
            float a2a[8]  = {a2v0.x, a2v0.y, a2v0.z, a2v0.w, a2v1.x, a2v1.y, a2v1.z, a2v1.w};
            float e2pa[8] = {e2pv0.x, e2pv0.y, e2pv0.z, e2pv0.w, e2pv1.x, e2pv1.y, e2pv1.z, e2pv1.w};
            float e2na[8] = {e2nv0.x, e2nv0.y, e2nv0.z, e2nv0.w, e2nv1.x, e2nv1.y, e2nv1.z, e2nv1.w};
            float dl = 0.f;
#pragma unroll
            for (int q = 0; q < 8; q++) {
                float ta = a1r + a2a[q];
                float w  = (ta >= 0.f) ? (e1pr * e2pa[q]) : (e1nr * e2na[q]);
                w = av[q] ? w : 0.f;
                w_s[wrow][wj + q] = w;
                dl += w;
            }
            den += dl;
        }
        __syncthreads();

        // ---- stage: accumulate out_tile += w_tile @ h_tile (packed f32x2) ----
#pragma unroll 8
        for (int jj = 0; jj < 32; jj++) {
            ulonglong2 u0 = *(const ulonglong2*)&hs[jj][tx * 8];
            ulonglong2 u1 = *(const ulonglong2*)&hs[jj][tx * 8 + 4];
#pragma unroll
            for (int r = 0; r < 4; r++) {
                float wv = w_s[ty * 4 + r][jj];
                unsigned long long wp = pack2(wv, wv);
                acc[r][0] = fma2(wp, u0.x, acc[r][0]);
                acc[r][1] = fma2(wp, u0.y, acc[r][1]);
                acc[r][2] = fma2(wp, u1.x, acc[r][2]);
                acc[r][3] = fma2(wp, u1.y, acc[r][3]);
            }
        }
    }

    // denominator: reduce across the 4 threads of each row-quad
    den += __shfl_xor_sync(0xffffffffu, den, 1);
    den += __shfl_xor_sync(0xffffffffu, den, 2);
    if ((t & 3) == 0) den_s[wrow] = den;
    __syncthreads();

#pragma unroll
    for (int r = 0; r < 4; r++) {
        float inv = 1.0f / den_s[ty * 4 + r];
        float o[8];
#pragma unroll
        for (int c = 0; c < 4; c++) {
            float x, y;
            unpack2(acc[r][c], x, y);
            o[c * 2]     = x * inv;
            o[c * 2 + 1] = y * inv;
        }
        float4 o0 = {o[0], o[1], o[2], o[3]};
        float4 o1 = {o[4], o[5], o[6], o[7]};
        size_t base = (size_t)(i0 + ty * 4 + r) * DOUT + tx * 8;
        *(float4*)&out[base]     = o0;
        *(float4*)&out[base + 4] = o1;
    }
}

// ============================================================
extern "C" void kernel_launch(void* const* d_in, const int* in_sizes, int n_in,
                              void* d_out, int out_size)
{
    const float* feat = (const float*)d_in[0];
    const int*   adj  = (const int*)d_in[1];
    const float* W    = (const float*)d_in[2];
    const float* b    = (const float*)d_in[3];
    const float* w1   = (const float*)d_in[4];
    const float* b1   = (const float*)d_in[5];
    const float* w2   = (const float*)d_in[6];
    const float* b2   = (const float*)d_in[7];
    float* out = (float*)d_out;

    gemm_h_kernel<<<NN / 64, 256>>>(feat, W, b);
    prep_kernel<<<NN / 8, 256>>>(w1, b1, w2, b2);
    attn_kernel<<<NN / 64, 256>>>(adj, out);
}

// round 3
// speedup vs baseline: 3.5370x; 3.5370x over previous
#include <cuda_runtime.h>
#include <cuda_bf16.h>
#include <math.h>
#include <cstdint>

#define NN   8192
#define DIN  256
#define DOUT 128

// ---------------- scratch ----------------
__device__ float g_h[NN * DOUT];                 // 4 MB fp32 h
__device__ float g_a1[NN], g_a2[NN];
__device__ float g_e1p[NN], g_e1n[NN];           // exp(a1), exp(0.01*a1)
__device__ float g_e2p[NN], g_e2n[NN];           // exp(a2), exp(0.01*a2)
__device__ unsigned short g_hT_hi[DOUT * NN];    // bf16 hT hi  [d][j]
__device__ unsigned short g_hT_lo[DOUT * NN];    // bf16 hT lo  [d][j]

// ---------------- helpers ----------------
__device__ __forceinline__ uint32_t smem_u32(const void* p) {
    uint32_t a;
    asm("{ .reg .u64 t; cvta.to.shared.u64 t, %1; cvt.u32.u64 %0, t; }" : "=r"(a) : "l"(p));
    return a;
}
__device__ __forceinline__ uint32_t pack_bf16x2(float lo, float hi) {
    uint32_t r;
    asm("cvt.rn.bf16x2.f32 %0, %1, %2;" : "=r"(r) : "f"(hi), "f"(lo));
    return r;
}
#define LDSM4(r0, r1, r2, r3, addr)                                            \
    asm volatile("ldmatrix.sync.aligned.m8n8.x4.shared.b16 {%0,%1,%2,%3}, [%4];" \
        : "=r"(r0), "=r"(r1), "=r"(r2), "=r"(r3) : "r"(addr))
#define MMA_BF16(c, a, b0, b1)                                                 \
    asm volatile("mma.sync.aligned.m16n8k16.row.col.f32.bf16.bf16.f32 "        \
        "{%0,%1,%2,%3},{%4,%5,%6,%7},{%8,%9},{%0,%1,%2,%3};"                   \
        : "+f"((c)[0]), "+f"((c)[1]), "+f"((c)[2]), "+f"((c)[3])               \
        : "r"((a)[0]), "r"((a)[1]), "r"((a)[2]), "r"((a)[3]), "r"(b0), "r"(b1))

// ============================================================
// Kernel 1: h = feat @ W^T + b
// ============================================================
__global__ __launch_bounds__(256) void gemm_h_kernel(
    const float* __restrict__ feat, const float* __restrict__ W, const float* __restrict__ bias)
{
    __shared__ float fs[64][32];
    __shared__ float ws[32][132];
    const int t = threadIdx.x;
    const int i0 = blockIdx.x * 64;
    const int ty = t >> 4, tx = t & 15;
    float acc[4][8];
#pragma unroll
    for (int r = 0; r < 4; r++)
#pragma unroll
        for (int c = 0; c < 8; c++) acc[r][c] = 0.f;

    for (int k0 = 0; k0 < DIN; k0 += 32) {
#pragma unroll
        for (int v = 0; v < 2; v++) {
            int f = v * 256 + t, row = f >> 3, off = (f & 7) * 4;
            *(float4*)&fs[row][off] = *(const float4*)&feat[(size_t)(i0 + row) * DIN + k0 + off];
        }
        {
            int c = t >> 1, half = (t & 1) * 16;
#pragma unroll
            for (int q = 0; q < 4; q++) {
                float4 wv = *(const float4*)&W[(size_t)c * DIN + k0 + half + q * 4];
                ws[half + q * 4 + 0][c] = wv.x; ws[half + q * 4 + 1][c] = wv.y;
                ws[half + q * 4 + 2][c] = wv.z; ws[half + q * 4 + 3][c] = wv.w;
            }
        }
        __syncthreads();
#pragma unroll
        for (int kk = 0; kk < 32; kk++) {
            float a[4];
#pragma unroll
            for (int r = 0; r < 4; r++) a[r] = fs[ty * 4 + r][kk];
            float4 b0 = *(const float4*)&ws[kk][tx * 8];
            float4 b1 = *(const float4*)&ws[kk][tx * 8 + 4];
            float bb[8] = {b0.x, b0.y, b0.z, b0.w, b1.x, b1.y, b1.z, b1.w};
#pragma unroll
            for (int r = 0; r < 4; r++)
#pragma unroll
                for (int c = 0; c < 8; c++) acc[r][c] += a[r] * bb[c];
        }
        __syncthreads();
    }
#pragma unroll
    for (int r = 0; r < 4; r++) {
        int gi = i0 + ty * 4 + r;
#pragma unroll
        for (int c = 0; c < 8; c++)
            g_h[(size_t)gi * DOUT + tx * 8 + c] = acc[r][c] + bias[tx * 8 + c];
    }
}

// ============================================================
// Kernel 2: a1,a2 + factorized exp tables
// ============================================================
__global__ __launch_bounds__(256) void prep_kernel(
    const float* __restrict__ w1, const float* __restrict__ b1,
    const float* __restrict__ w2, const float* __restrict__ b2)
{
    const int warp = threadIdx.x >> 5, lane = threadIdx.x & 31;
    const int i = blockIdx.x * 8 + warp;
    float s1 = 0.f, s2 = 0.f;
#pragma unroll
    for (int d = lane; d < DOUT; d += 32) {
        float hv = g_h[(size_t)i * DOUT + d];
        s1 += hv * w1[d]; s2 += hv * w2[d];
    }
#pragma unroll
    for (int o = 16; o > 0; o >>= 1) {
        s1 += __shfl_xor_sync(0xffffffffu, s1, o);
        s2 += __shfl_xor_sync(0xffffffffu, s2, o);
    }
    if (lane == 0) {
        float a1 = s1 + b1[0], a2 = s2 + b2[0];
        g_a1[i] = a1; g_a2[i] = a2;
        g_e1p[i] = expf(a1); g_e1n[i] = expf(0.01f * a1);
        g_e2p[i] = expf(a2); g_e2n[i] = expf(0.01f * a2);
    }
}

// ============================================================
// Kernel 3: transpose + bf16 hi/lo split of h -> g_hT_hi/lo [d][j]
// ============================================================
__global__ __launch_bounds__(256) void convert_hT_kernel()
{
    __shared__ float s[32][33];
    const int i0 = blockIdx.x * 32, d0 = blockIdx.y * 32;
    const int lx = threadIdx.x & 31, ly = threadIdx.x >> 5;
#pragma unroll
    for (int q = 0; q < 4; q++) {
        int il = ly + q * 8;
        s[il][lx] = g_h[(size_t)(i0 + il) * DOUT + d0 + lx];
    }
    __syncthreads();
#pragma unroll
    for (int q = 0; q < 4; q++) {
        int dl = ly + q * 8;
        float v = s[lx][dl];
        uint32_t u = __float_as_uint(v);
        float hi = __uint_as_float(u & 0xffff0000u);
        float lo = v - hi;
        __nv_bfloat16 bl = __float2bfloat16(lo);
        size_t idx = (size_t)(d0 + dl) * NN + i0 + lx;
        g_hT_hi[idx] = (unsigned short)(u >> 16);
        g_hT_lo[idx] = *reinterpret_cast<unsigned short*>(&bl);
    }
}

// ============================================================
// Kernel 4: fused attention via ldmatrix + mma.sync (bf16 split)
// 128 blocks x 256 threads; CTA tile M=64 x N=128, K-tile 64.
// Warp grid 2(m) x 4(n): warp tile m32 x n32.
// SMEM per buf: A_hi 8K | A_lo 8K | B_hi 16K | B_lo 16K = 48K; x2 = 96K
// ============================================================
#define KT      64
#define A_HI    0
#define A_LO    8192
#define B_HI    16384
#define B_LO    32768
#define BUFS    49152
#define ATTN_SMEM (2 * BUFS)

__global__ __launch_bounds__(256) void attn_mma_kernel(
    const int* __restrict__ adj, float* __restrict__ out)
{
    extern __shared__ char smem[];
    __shared__ float den_s[64];
    const uint32_t sb = smem_u32(smem);
    const int t = threadIdx.x, lane = t & 31, wid = t >> 5;
    const int i0 = blockIdx.x * 64;

    // ---- weight-gen mapping: thread (rq, jq): rows rq+16u (u<4), j's jq*4..+3 ----
    const int jq = t & 15, rq = t >> 4;
    float a1r[4], e1pv[4], e1nv[4], den[4];
    const int* adjp[4];
#pragma unroll
    for (int u = 0; u < 4; u++) {
        int gi = i0 + rq + 16 * u;
        a1r[u] = g_a1[gi]; e1pv[u] = g_e1p[gi]; e1nv[u] = g_e1n[gi];
        den[u] = 0.f;
        adjp[u] = adj + (size_t)gi * NN + jq * 4;
    }

    // ---- B copy mapping: row bn (=d), half bhalf (32 j's) ----
    const int bn = t >> 1, bhalf = t & 1;
    const unsigned short* srcH = g_hT_hi + (size_t)bn * NN + bhalf * 32;
    const unsigned short* srcL = g_hT_lo + (size_t)bn * NN + bhalf * 32;
    const uint32_t bRowW = bn * 128;
    const uint32_t bXorW = (bn & 7) << 4;

    // ---- mma mapping ----
    const int wm = wid >> 2, wn = wid & 3;
    uint32_t aRowOff[2], bRowOff[2];
#pragma unroll
    for (int m = 0; m < 2; m++)
        aRowOff[m] = (uint32_t)(wm * 32 + m * 16 + (lane & 15)) * 128;
#pragma unroll
    for (int p = 0; p < 2; p++)
        bRowOff[p] = (uint32_t)(wn * 32 + p * 16 + (lane & 7) + ((lane >> 4) << 3)) * 128;
    const uint32_t mXor = (lane & 7) << 4;
    const uint32_t aCol = (lane >> 4) << 4;
    const uint32_t bCol = (lane & 8) << 1;

    float acc[32];
#pragma unroll
    for (int i = 0; i < 32; i++) acc[i] = 0.f;

    // ---- prefetch regs ----
    int4 adjR[4]; uint4 hHR[4], hLR[4]; float4 a2R, epR, enR;
    auto prefetch = [&](int J0) {
#pragma unroll
        for (int u = 0; u < 4; u++) adjR[u] = *(const int4*)(adjp[u] + J0);
#pragma unroll
        for (int q = 0; q < 4; q++) {
            hHR[q] = ((const uint4*)(srcH + J0))[q];
            hLR[q] = ((const uint4*)(srcL + J0))[q];
        }
        a2R = *(const float4*)&g_a2[J0 + jq * 4];
        epR = *(const float4*)&g_e2p[J0 + jq * 4];
        enR = *(const float4*)&g_e2n[J0 + jq * 4];
    };
    prefetch(0);

    for (int k = 0; k < NN / KT; k++) {
        const uint32_t bufb = (k & 1) ? BUFS : 0;

        // ---- STS B (hi/lo), swizzled ----
#pragma unroll
        for (int q = 0; q < 4; q++) {
            uint32_t off = bRowW + ((bhalf * 64 + q * 16) ^ bXorW);
            *(uint4*)(smem + bufb + B_HI + off) = hHR[q];
            *(uint4*)(smem + bufb + B_LO + off) = hLR[q];
        }
        // ---- weights: compute, split, STS A ----
        {
            float a2a[4] = {a2R.x, a2R.y, a2R.z, a2R.w};
            float epa[4] = {epR.x, epR.y, epR.z, epR.w};
            float ena[4] = {enR.x, enR.y, enR.z, enR.w};
#pragma unroll
            for (int u = 0; u < 4; u++) {
                int avi[4] = {adjR[u].x, adjR[u].y, adjR[u].z, adjR[u].w};
                float w[4];
#pragma unroll
                for (int q = 0; q < 4; q++) {
                    float ta = a1r[u] + a2a[q];
                    float e1 = (ta >= 0.f) ? e1pv[u] : e1nv[u];
                    float e2 = (ta >= 0.f) ? epa[q] : ena[q];
                    float wq = e1 * e2;
                    wq = avi[q] ? wq : 0.f;
                    den[u] += wq;
                    w[q] = wq;
                }
                uint32_t u0 = __float_as_uint(w[0]), u1 = __float_as_uint(w[1]);
                uint32_t u2 = __float_as_uint(w[2]), u3 = __float_as_uint(w[3]);
                uint32_t hi0 = __byte_perm(u0, u1, 0x7632);
                uint32_t hi1 = __byte_perm(u2, u3, 0x7632);
                float l0 = w[0] - __uint_as_float(u0 & 0xffff0000u);
                float l1 = w[1] - __uint_as_float(u1 & 0xffff0000u);
                float l2 = w[2] - __uint_as_float(u2 & 0xffff0000u);
                float l3 = w[3] - __uint_as_float(u3 & 0xffff0000u);
                uint32_t lo0 = pack_bf16x2(l0, l1);
                uint32_t lo1 = pack_bf16x2(l2, l3);
                int row = rq + 16 * u;
                uint32_t off = row * 128 + ((jq * 8) ^ ((row & 7) << 4));
                *(uint2*)(smem + bufb + A_HI + off) = make_uint2(hi0, hi1);
                *(uint2*)(smem + bufb + A_LO + off) = make_uint2(lo0, lo1);
            }
        }
        __syncthreads();

        // ---- prefetch next tile (overlaps with mma below) ----
        {
            int j0n = (k + 1 < NN / KT) ? (k + 1) * KT : 0;
            prefetch(j0n);
        }

        // ---- mma over 4 k16 steps ----
        const uint32_t ab = sb + bufb;
#pragma unroll
        for (int s = 0; s < 4; s++) {
            const uint32_t cs = s * 32;
            uint32_t ah[2][4], al[2][4], bh[2][4], bl[2][4];
            const uint32_t ca = (cs + aCol) ^ mXor;
            const uint32_t cb = (cs + bCol) ^ mXor;
#pragma unroll
            for (int m = 0; m < 2; m++) {
                LDSM4(ah[m][0], ah[m][1], ah[m][2], ah[m][3], ab + A_HI + aRowOff[m] + ca);
                LDSM4(al[m][0], al[m][1], al[m][2], al[m][3], ab + A_LO + aRowOff[m] + ca);
            }
#pragma unroll
            for (int p = 0; p < 2; p++) {
                LDSM4(bh[p][0], bh[p][1], bh[p][2], bh[p][3], ab + B_HI + bRowOff[p] + cb);
                LDSM4(bl[p][0], bl[p][1], bl[p][2], bl[p][3], ab + B_LO + bRowOff[p] + cb);
            }
#pragma unroll
            for (int m = 0; m < 2; m++)
#pragma unroll
                for (int nt = 0; nt < 4; nt++) {
                    float* c = &acc[(m * 4 + nt) * 4];
                    uint32_t b0 = bh[nt >> 1][(nt & 1) * 2], b1 = bh[nt >> 1][(nt & 1) * 2 + 1];
                    MMA_BF16(c, ah[m], b0, b1);
                    MMA_BF16(c, al[m], b0, b1);
                    uint32_t d0 = bl[nt >> 1][(nt & 1) * 2], d1 = bl[nt >> 1][(nt & 1) * 2 + 1];
                    MMA_BF16(c, ah[m], d0, d1);
                }
        }
        __syncthreads();
    }

    // ---- denominator reduce over jq (16 lanes) ----
#pragma unroll
    for (int o = 8; o > 0; o >>= 1)
#pragma unroll
        for (int u = 0; u < 4; u++) den[u] += __shfl_xor_sync(0xffffffffu, den[u], o);
    if (jq == 0)
#pragma unroll
        for (int u = 0; u < 4; u++) den_s[rq + 16 * u] = den[u];
    __syncthreads();

    // ---- epilogue ----
#pragma unroll
    for (int m = 0; m < 2; m++) {
        int r0 = wm * 32 + m * 16 + (lane >> 2);
        float inv0 = 1.0f / den_s[r0];
        float inv1 = 1.0f / den_s[r0 + 8];
#pragma unroll
        for (int nt = 0; nt < 4; nt++) {
            float* c = &acc[(m * 4 + nt) * 4];
            int col = wn * 32 + nt * 8 + (lane & 3) * 2;
            *(float2*)&out[(size_t)(i0 + r0) * DOUT + col]     = make_float2(c[0] * inv0, c[1] * inv0);
            *(float2*)&out[(size_t)(i0 + r0 + 8) * DOUT + col] = make_float2(c[2] * inv1, c[3] * inv1);
        }
    }
}

// ============================================================
extern "C" void kernel_launch(void* const* d_in, const int* in_sizes, int n_in,
                              void* d_out, int out_size)
{
    const float* feat = (const float*)d_in[0];
    const int*   adj  = (const int*)d_in[1];
    const float* W    = (const float*)d_in[2];
    const float* b    = (const float*)d_in[3];
    const float* w1   = (const float*)d_in[4];
    const float* b1   = (const float*)d_in[5];
    const float* w2   = (const float*)d_in[6];
    const float* b2   = (const float*)d_in[7];
    float* out = (float*)d_out;

    static bool attr_set = false;
    if (!attr_set) {
        cudaFuncSetAttribute(attn_mma_kernel,
                             cudaFuncAttributeMaxDynamicSharedMemorySize, ATTN_SMEM);
        attr_set = true;
    }

    gemm_h_kernel<<<NN / 64, 256>>>(feat, W, b);
    prep_kernel<<<NN / 8, 256>>>(w1, b1, w2, b2);
    convert_hT_kernel<<<dim3(NN / 32, DOUT / 32), 256>>>();
    attn_mma_kernel<<<NN / 64, 256, ATTN_SMEM>>>(adj, out);
}